// round 1
// baseline (speedup 1.0000x reference)
#include <cuda_runtime.h>
#include <math.h>
#include <stdint.h>

#define B_  2
#define T_  2048
#define D_  1024
#define H_  16
#define DH_ 64
#define NTOK (B_*T_)          // 4096

// ---------------- scratch (device globals; no allocation) ----------------
__device__ float g_integral[(size_t)NTOK * D_];            // 16 MB
__device__ float g_params[(size_t)NTOK * 12];              // g0,g1,g2,kickmul per projection
__device__ float g_abc[(size_t)3 * NTOK * 3 * D_];         // 151 MB : per-proj [a|i|d] rows (K=3072)
__device__ float g_q[(size_t)NTOK * D_];
__device__ float g_k[(size_t)NTOK * D_];
__device__ float g_v[(size_t)NTOK * D_];
__device__ float g_att[(size_t)NTOK * D_];

// ---------------- per-token reductions: norms, cos, kick, gates ----------------
__global__ void token_stats_kernel(const float* __restrict__ x,
                                   const float* __restrict__ gate_w,   // (3,3,D)
                                   const float* __restrict__ gate_b,   // (3,3)
                                   const float* __restrict__ kick_w,   // (3,1,D)
                                   const float* __restrict__ kick_b)   // (3,1)
{
    int r = blockIdx.x;            // token index
    int t = r % T_;
    const float* xt = x + (size_t)r * D_;
    int tid = threadIdx.x;         // 128 threads

    float acc[15];
#pragma unroll
    for (int v = 0; v < 15; v++) acc[v] = 0.f;

    for (int d = tid; d < D_; d += 128) {
        float xv = xt[d];
        float pv = (t > 0) ? xt[d - D_] : 0.f;
        acc[0] = fmaf(xv, xv, acc[0]);
        acc[1] = fmaf(xv, pv, acc[1]);
        acc[2] = fmaf(pv, pv, acc[2]);
        acc[3] = fmaf(xv, kick_w[0 * D_ + d], acc[3]);
        acc[4] = fmaf(xv, kick_w[1 * D_ + d], acc[4]);
        acc[5] = fmaf(xv, kick_w[2 * D_ + d], acc[5]);
#pragma unroll
        for (int j = 0; j < 9; j++)
            acc[6 + j] = fmaf(xv, gate_w[j * D_ + d], acc[6 + j]);
    }

#pragma unroll
    for (int v = 0; v < 15; v++)
#pragma unroll
        for (int off = 16; off; off >>= 1)
            acc[v] += __shfl_down_sync(0xffffffffu, acc[v], off);

    __shared__ float red[15][4];
    int w = tid >> 5, l = tid & 31;
    if (l == 0)
#pragma unroll
        for (int v = 0; v < 15; v++) red[v][w] = acc[v];
    __syncthreads();

    if (tid == 0) {
        float s[15];
#pragma unroll
        for (int v = 0; v < 15; v++)
            s[v] = red[v][0] + red[v][1] + red[v][2] + red[v][3];

        float nt = fmaxf(sqrtf(s[0]), 1e-12f);
        float np = fmaxf(sqrtf(s[2]), 1e-12f);
        float cosv = (t > 0) ? s[1] / (nt * np) : 0.f;
        float stag = (cosv > 0.95f) ? 1.f : 0.f;

        float* out = g_params + (size_t)r * 12;
#pragma unroll
        for (int p = 0; p < 3; p++) {
            float ks = 1.f / (1.f + expf(-(s[3 + p] + kick_b[p])));
            float l0 = s[6 + p * 3 + 0] + gate_b[p * 3 + 0];
            float l1 = s[6 + p * 3 + 1] + gate_b[p * 3 + 1];
            float l2 = s[6 + p * 3 + 2] + gate_b[p * 3 + 2];
            float m = fmaxf(l0, fmaxf(l1, l2));
            float e0 = expf(l0 - m), e1 = expf(l1 - m), e2 = expf(l2 - m);
            float inv = 1.f / (e0 + e1 + e2);
            float g0 = fminf(e0 * inv, 0.6f);
            float g1 = fminf(e1 * inv, 0.6f);
            float g2 = fminf(e2 * inv, 0.6f);
            g1 = fmaxf(g1, 0.25f);
            float gi = 1.f / (g0 + g1 + g2);
            out[p * 4 + 0] = g0 * gi;
            out[p * 4 + 1] = g1 * gi;
            out[p * 4 + 2] = g2 * gi;
            out[p * 4 + 3] = stag * ks;    // kick multiplier (stag * kick_strength)
        }
    }
}

// ---------------- EMA (integral) : one thread per (b,d) channel ----------------
__global__ void ema_kernel(const float* __restrict__ x)
{
    int c = blockIdx.x * blockDim.x + threadIdx.x;
    if (c >= B_ * D_) return;
    int b = c / D_, d = c % D_;
    const float* xp = x + (size_t)b * T_ * D_ + d;
    float* ip = g_integral + (size_t)b * T_ * D_ + d;
    float acc = xp[0];
    ip[0] = acc;
#pragma unroll 8
    for (int t = 1; t < T_; t++) {
        acc = fmaf(0.95f, acc, 0.05f * xp[(size_t)t * D_]);
        ip[(size_t)t * D_] = acc;
    }
}

// ---------------- build gated GEMM inputs [g0*x | g1*integral | g2*deriv'] ----------------
__global__ void build_abc_kernel(const float* __restrict__ x,
                                 const float* __restrict__ kick_v)   // (3,D)
{
    int r = blockIdx.x;           // token
    int p = blockIdx.y;           // projection 0..2
    int t = r % T_;
    const float* par = g_params + (size_t)r * 12 + p * 4;
    float g0 = par[0], g1 = par[1], g2 = par[2], km = par[3];
    float* dst = g_abc + ((size_t)p * NTOK + r) * (3 * D_);
    const float* xt = x + (size_t)r * D_;
    const float* integ = g_integral + (size_t)r * D_;
    for (int d = threadIdx.x; d < D_; d += blockDim.x) {
        float xv = xt[d];
        float der = (t > 0) ? (xv - xt[d - D_]) : 0.f;
        der = fmaf(km, kick_v[p * D_ + d], der);
        dst[d]          = g0 * xv;
        dst[D_ + d]     = g1 * integ[d];
        dst[2 * D_ + d] = g2 * der;
    }
}

// ---------------- fp32 SGEMM: C(MxN) = A(MxK) * W^T, W selected per 1024-K range ----------------
// A row-major (lda), W row-major (N x 1024) -- B[k][n] = Wsel[n*1024 + k%1024]
__global__ void __launch_bounds__(256, 2)
sgemm_kernel(const float* __restrict__ A, int lda,
             const float* __restrict__ W0, const float* __restrict__ W1,
             const float* __restrict__ W2,
             float* __restrict__ C, int N, int K)
{
    __shared__ float As[8][128];
    __shared__ float Bs[8][128];

    int tid = threadIdx.x;
    int m0 = blockIdx.y * 128;
    int n0 = blockIdx.x * 128;
    int ty = tid >> 4;             // 0..15
    int tx = tid & 15;             // 0..15
    int lr = tid >> 1;             // 0..127
    int lc = (tid & 1) * 4;        // 0 or 4

    float acc[8][8];
#pragma unroll
    for (int i = 0; i < 8; i++)
#pragma unroll
        for (int j = 0; j < 8; j++) acc[i][j] = 0.f;

    const float* Wsel[3] = {W0, W1, W2};

    for (int k0 = 0; k0 < K; k0 += 8) {
        // A tile (128 rows x 8 k) -> As[k][m]
        float4 av = *(const float4*)(A + (size_t)(m0 + lr) * lda + k0 + lc);
        As[lc + 0][lr] = av.x; As[lc + 1][lr] = av.y;
        As[lc + 2][lr] = av.z; As[lc + 3][lr] = av.w;
        // W tile (128 n x 8 k) -> Bs[k][n]
        const float* W = Wsel[k0 >> 10];
        int kk = k0 & 1023;
        float4 bv = *(const float4*)(W + (size_t)(n0 + lr) * 1024 + kk + lc);
        Bs[lc + 0][lr] = bv.x; Bs[lc + 1][lr] = bv.y;
        Bs[lc + 2][lr] = bv.z; Bs[lc + 3][lr] = bv.w;
        __syncthreads();

#pragma unroll
        for (int k = 0; k < 8; k++) {
            float4 a0 = *(const float4*)&As[k][ty * 8];
            float4 a1 = *(const float4*)&As[k][ty * 8 + 4];
            float4 b0 = *(const float4*)&Bs[k][tx * 8];
            float4 b1 = *(const float4*)&Bs[k][tx * 8 + 4];
            float a[8] = {a0.x, a0.y, a0.z, a0.w, a1.x, a1.y, a1.z, a1.w};
            float b[8] = {b0.x, b0.y, b0.z, b0.w, b1.x, b1.y, b1.z, b1.w};
#pragma unroll
            for (int i = 0; i < 8; i++)
#pragma unroll
                for (int j = 0; j < 8; j++)
                    acc[i][j] = fmaf(a[i], b[j], acc[i][j]);
        }
        __syncthreads();
    }

#pragma unroll
    for (int i = 0; i < 8; i++) {
        float* cp = C + (size_t)(m0 + ty * 8 + i) * N + n0 + tx * 8;
        float4 c0 = {acc[i][0], acc[i][1], acc[i][2], acc[i][3]};
        float4 c1 = {acc[i][4], acc[i][5], acc[i][6], acc[i][7]};
        *(float4*)(cp)     = c0;
        *(float4*)(cp + 4) = c1;
    }
}

// ---------------- sparse dilated attention: one warp per (b,h,t) ----------------
// valid count recomputed analytically: 1 + min(3,t) + max(0, floor(log2 t) - 1)
template<int AA>
__global__ void attn_kernel(const int* __restrict__ positions)
{
    int wid = (blockIdx.x * blockDim.x + threadIdx.x) >> 5;
    int lane = threadIdx.x & 31;
    if (wid >= B_ * H_ * T_) return;
    int t = wid % T_;
    int h = (wid / T_) % H_;
    int b = wid / (T_ * H_);

    const float* qp = g_q + ((size_t)b * T_ + t) * D_ + h * DH_;
    int d0 = lane * 2;
    float q0 = qp[d0], q1 = qp[d0 + 1];

    int nv = 1 + min(3, t);
    if (t >= 4) nv += (31 - __clz((unsigned)t)) - 1;

    float sc[AA];
    int ps[AA];
    float mx = -1e30f;
#pragma unroll
    for (int a = 0; a < AA; a++) {
        int pos = positions[t * AA + a];
        ps[a] = pos;
        const float* kp = g_k + ((size_t)b * T_ + pos) * D_ + h * DH_;
        float s = fmaf(q0, kp[d0], q1 * kp[d0 + 1]);
#pragma unroll
        for (int o = 16; o; o >>= 1) s += __shfl_xor_sync(0xffffffffu, s, o);
        s = (a < nv) ? s * 0.125f : -1e30f;
        sc[a] = s;
        mx = fmaxf(mx, s);
    }
    float sum = 0.f;
#pragma unroll
    for (int a = 0; a < AA; a++) { sc[a] = expf(sc[a] - mx); sum += sc[a]; }
    float inv = 1.f / sum;
    float o0 = 0.f, o1 = 0.f;
#pragma unroll
    for (int a = 0; a < AA; a++) {
        const float* vp = g_v + ((size_t)b * T_ + ps[a]) * D_ + h * DH_;
        float wgt = sc[a] * inv;
        o0 = fmaf(wgt, vp[d0], o0);
        o1 = fmaf(wgt, vp[d0 + 1], o1);
    }
    float* op = g_att + ((size_t)b * T_ + t) * D_ + h * DH_;
    op[d0] = o0;
    op[d0 + 1] = o1;
}

// dynamic-A fallback (uses local arrays; only used if A != 15)
__global__ void attn_kernel_dyn(const int* __restrict__ positions, int A)
{
    int wid = (blockIdx.x * blockDim.x + threadIdx.x) >> 5;
    int lane = threadIdx.x & 31;
    if (wid >= B_ * H_ * T_) return;
    int t = wid % T_;
    int h = (wid / T_) % H_;
    int b = wid / (T_ * H_);
    const float* qp = g_q + ((size_t)b * T_ + t) * D_ + h * DH_;
    int d0 = lane * 2;
    float q0 = qp[d0], q1 = qp[d0 + 1];
    int nv = 1 + min(3, t);
    if (t >= 4) nv += (31 - __clz((unsigned)t)) - 1;
    float sc[32]; int ps[32];
    float mx = -1e30f;
    for (int a = 0; a < A; a++) {
        int pos = positions[t * A + a];
        ps[a] = pos;
        const float* kp = g_k + ((size_t)b * T_ + pos) * D_ + h * DH_;
        float s = fmaf(q0, kp[d0], q1 * kp[d0 + 1]);
        for (int o = 16; o; o >>= 1) s += __shfl_xor_sync(0xffffffffu, s, o);
        s = (a < nv) ? s * 0.125f : -1e30f;
        sc[a] = s; mx = fmaxf(mx, s);
    }
    float sum = 0.f;
    for (int a = 0; a < A; a++) { sc[a] = expf(sc[a] - mx); sum += sc[a]; }
    float inv = 1.f / sum;
    float o0 = 0.f, o1 = 0.f;
    for (int a = 0; a < A; a++) {
        const float* vp = g_v + ((size_t)b * T_ + ps[a]) * D_ + h * DH_;
        float wgt = sc[a] * inv;
        o0 = fmaf(wgt, vp[d0], o0);
        o1 = fmaf(wgt, vp[d0 + 1], o1);
    }
    float* op = g_att + ((size_t)b * T_ + t) * D_ + h * DH_;
    op[d0] = o0; op[d0 + 1] = o1;
}

// ---------------- launcher ----------------
extern "C" void kernel_launch(void* const* d_in, const int* in_sizes, int n_in,
                              void* d_out, int out_size)
{
    const float* x       = (const float*)d_in[0];
    const float* qkv_Wp  = (const float*)d_in[1];   // (3,1024,1024)
    const float* qkv_Wi  = (const float*)d_in[2];
    const float* qkv_Wd  = (const float*)d_in[3];
    const float* gate_w  = (const float*)d_in[4];   // (3,3,1024)
    const float* gate_b  = (const float*)d_in[5];   // (3,3)
    const float* kick_v  = (const float*)d_in[6];   // (3,1024)
    const float* kick_w  = (const float*)d_in[7];   // (3,1,1024)
    const float* kick_b  = (const float*)d_in[8];   // (3,1)
    const float* o_w     = (const float*)d_in[9];   // (1024,1024)
    const int*   positions = (const int*)d_in[10];  // (T, A)
    int A = in_sizes[10] / T_;

    float* out = (float*)d_out;

    // device pointers for scratch globals
    void *p_abc, *p_q, *p_k, *p_v, *p_att;
    cudaGetSymbolAddress(&p_abc, g_abc);
    cudaGetSymbolAddress(&p_q, g_q);
    cudaGetSymbolAddress(&p_k, g_k);
    cudaGetSymbolAddress(&p_v, g_v);
    cudaGetSymbolAddress(&p_att, g_att);
    float* abc = (float*)p_abc;
    float* qkv_out[3] = {(float*)p_q, (float*)p_k, (float*)p_v};

    // 1. per-token gates / kick / stagnation
    token_stats_kernel<<<NTOK, 128>>>(x, gate_w, gate_b, kick_w, kick_b);

    // 2. EMA integral
    ema_kernel<<<(B_ * D_ + 255) / 256, 256>>>(x);

    // 3. gated GEMM inputs for all 3 projections
    dim3 gb(NTOK, 3);
    build_abc_kernel<<<gb, 256>>>(x, kick_v);

    // 4. projection GEMMs: (4096 x 3072) * blockdiag(Wp,Wi,Wd)^T -> q/k/v
    dim3 ggrid(1024 / 128, NTOK / 128);   // (8, 32)
    for (int p = 0; p < 3; p++) {
        sgemm_kernel<<<ggrid, 256>>>(
            abc + (size_t)p * NTOK * 3 * D_, 3 * D_,
            qkv_Wp + (size_t)p * D_ * D_,
            qkv_Wi + (size_t)p * D_ * D_,
            qkv_Wd + (size_t)p * D_ * D_,
            qkv_out[p], D_, 3 * D_);
    }

    // 5. sparse dilated attention
    int nwarps = B_ * H_ * T_;
    int nblocks = nwarps / 4;            // 128 threads = 4 warps per block
    if (A == 15)
        attn_kernel<15><<<nblocks, 128>>>(positions);
    else
        attn_kernel_dyn<<<nblocks, 128>>>(positions, A);

    // 6. output projection: (4096 x 1024) * o_w^T -> d_out
    sgemm_kernel<<<ggrid, 256>>>((float*)p_att, D_, o_w, o_w, o_w, out, D_, D_);
}

// round 3
// speedup vs baseline: 1.5209x; 1.5209x over previous
#include <cuda_runtime.h>
#include <cuda_bf16.h>
#include <math.h>
#include <stdint.h>

#define B_  2
#define T_  2048
#define D_  1024
#define H_  16
#define DH_ 64
#define NTOK (B_*T_)          // 4096
#define K3  3072

// ---------------- scratch (device globals; no allocation) ----------------
__device__ __align__(256) float g_integral[(size_t)NTOK * D_];
__device__ float g_params[(size_t)NTOK * 12];
__device__ __align__(256) __nv_bfloat16 g_abc_hi[(size_t)3 * NTOK * K3];
__device__ __align__(256) __nv_bfloat16 g_abc_lo[(size_t)3 * NTOK * K3];
__device__ __align__(256) __nv_bfloat16 g_w_hi[(size_t)3 * 1024 * K3];
__device__ __align__(256) __nv_bfloat16 g_w_lo[(size_t)3 * 1024 * K3];
__device__ __align__(256) __nv_bfloat16 g_ow_hi[(size_t)1024 * 1024];
__device__ __align__(256) __nv_bfloat16 g_ow_lo[(size_t)1024 * 1024];
__device__ __align__(256) float g_q[(size_t)NTOK * D_];
__device__ __align__(256) float g_k[(size_t)NTOK * D_];
__device__ __align__(256) float g_v[(size_t)NTOK * D_];
__device__ __align__(256) __nv_bfloat16 g_att_hi[(size_t)NTOK * D_];
__device__ __align__(256) __nv_bfloat16 g_att_lo[(size_t)NTOK * D_];

// ============================ PTX helpers (sm_100-baseline safe) ============================
__device__ __forceinline__ uint32_t s2u(const void* p) {
    uint32_t a;
    asm("{ .reg .u64 t; cvta.to.shared.u64 t, %1; cvt.u32.u64 %0, t; }" : "=r"(a) : "l"(p));
    return a;
}
__device__ __forceinline__ void cp_async16(uint32_t dst, const void* src) {
    asm volatile("cp.async.cg.shared.global [%0], [%1], 16;" :: "r"(dst), "l"(src));
}
__device__ __forceinline__ void cp_commit() {
    asm volatile("cp.async.commit_group;" ::: "memory");
}
__device__ __forceinline__ void cp_wait3() {
    asm volatile("cp.async.wait_group 3;" ::: "memory");
}
__device__ __forceinline__ void ldsm_x4(uint32_t* r, uint32_t addr) {
    asm volatile("ldmatrix.sync.aligned.m8n8.x4.shared.b16 {%0,%1,%2,%3}, [%4];"
        : "=r"(r[0]), "=r"(r[1]), "=r"(r[2]), "=r"(r[3]) : "r"(addr));
}
__device__ __forceinline__ void mma_bf16(float* d, const uint32_t* a, const uint32_t* b) {
    asm volatile(
        "mma.sync.aligned.m16n8k16.row.col.f32.bf16.bf16.f32 "
        "{%0,%1,%2,%3}, {%4,%5,%6,%7}, {%8,%9}, {%0,%1,%2,%3};"
        : "+f"(d[0]), "+f"(d[1]), "+f"(d[2]), "+f"(d[3])
        : "r"(a[0]), "r"(a[1]), "r"(a[2]), "r"(a[3]), "r"(b[0]), "r"(b[1]));
}

// ============================ misc kernels ============================
__global__ void token_stats_kernel(const float* __restrict__ x,
                                   const float* __restrict__ gate_w,
                                   const float* __restrict__ gate_b,
                                   const float* __restrict__ kick_w,
                                   const float* __restrict__ kick_b)
{
    int r = blockIdx.x;
    int t = r % T_;
    const float* xt = x + (size_t)r * D_;
    int tid = threadIdx.x;

    float acc[15];
#pragma unroll
    for (int v = 0; v < 15; v++) acc[v] = 0.f;

    for (int d = tid; d < D_; d += 128) {
        float xv = xt[d];
        float pv = (t > 0) ? xt[d - D_] : 0.f;
        acc[0] = fmaf(xv, xv, acc[0]);
        acc[1] = fmaf(xv, pv, acc[1]);
        acc[2] = fmaf(pv, pv, acc[2]);
        acc[3] = fmaf(xv, kick_w[0 * D_ + d], acc[3]);
        acc[4] = fmaf(xv, kick_w[1 * D_ + d], acc[4]);
        acc[5] = fmaf(xv, kick_w[2 * D_ + d], acc[5]);
#pragma unroll
        for (int j = 0; j < 9; j++)
            acc[6 + j] = fmaf(xv, gate_w[j * D_ + d], acc[6 + j]);
    }
#pragma unroll
    for (int v = 0; v < 15; v++)
#pragma unroll
        for (int off = 16; off; off >>= 1)
            acc[v] += __shfl_down_sync(0xffffffffu, acc[v], off);

    __shared__ float red[15][4];
    int w = tid >> 5, l = tid & 31;
    if (l == 0)
#pragma unroll
        for (int v = 0; v < 15; v++) red[v][w] = acc[v];
    __syncthreads();

    if (tid == 0) {
        float s[15];
#pragma unroll
        for (int v = 0; v < 15; v++)
            s[v] = red[v][0] + red[v][1] + red[v][2] + red[v][3];
        float nt = fmaxf(sqrtf(s[0]), 1e-12f);
        float np = fmaxf(sqrtf(s[2]), 1e-12f);
        float cosv = (t > 0) ? s[1] / (nt * np) : 0.f;
        float stag = (cosv > 0.95f) ? 1.f : 0.f;
        float* out = g_params + (size_t)r * 12;
#pragma unroll
        for (int p = 0; p < 3; p++) {
            float ks = 1.f / (1.f + expf(-(s[3 + p] + kick_b[p])));
            float l0 = s[6 + p * 3 + 0] + gate_b[p * 3 + 0];
            float l1 = s[6 + p * 3 + 1] + gate_b[p * 3 + 1];
            float l2 = s[6 + p * 3 + 2] + gate_b[p * 3 + 2];
            float m = fmaxf(l0, fmaxf(l1, l2));
            float e0 = expf(l0 - m), e1 = expf(l1 - m), e2 = expf(l2 - m);
            float inv = 1.f / (e0 + e1 + e2);
            float g0 = fminf(e0 * inv, 0.6f);
            float g1 = fminf(e1 * inv, 0.6f);
            float g2 = fminf(e2 * inv, 0.6f);
            g1 = fmaxf(g1, 0.25f);
            float gi = 1.f / (g0 + g1 + g2);
            out[p * 4 + 0] = g0 * gi;
            out[p * 4 + 1] = g1 * gi;
            out[p * 4 + 2] = g2 * gi;
            out[p * 4 + 3] = stag * ks;
        }
    }
}

__global__ void ema_kernel(const float* __restrict__ x)
{
    int c = blockIdx.x * blockDim.x + threadIdx.x;
    if (c >= B_ * D_) return;
    int b = c / D_, d = c % D_;
    const float* xp = x + (size_t)b * T_ * D_ + d;
    float* ip = g_integral + (size_t)b * T_ * D_ + d;
    float acc = xp[0];
    ip[0] = acc;
#pragma unroll 8
    for (int t = 1; t < T_; t++) {
        acc = fmaf(0.95f, acc, 0.05f * xp[(size_t)t * D_]);
        ip[(size_t)t * D_] = acc;
    }
}

__device__ __forceinline__ void split_store(__nv_bfloat16* hi, __nv_bfloat16* lo,
                                            size_t idx, float v) {
    __nv_bfloat16 h = __float2bfloat16(v);
    hi[idx] = h;
    lo[idx] = __float2bfloat16(v - __bfloat162float(h));
}

__global__ void build_abc_kernel(const float* __restrict__ x,
                                 const float* __restrict__ kick_v)
{
    int r = blockIdx.x;
    int p = blockIdx.y;
    int t = r % T_;
    const float* par = g_params + (size_t)r * 12 + p * 4;
    float g0 = par[0], g1 = par[1], g2 = par[2], km = par[3];
    size_t base = ((size_t)p * NTOK + r) * K3;
    const float* xt = x + (size_t)r * D_;
    const float* integ = g_integral + (size_t)r * D_;
    for (int d = threadIdx.x; d < D_; d += blockDim.x) {
        float xv = xt[d];
        float der = (t > 0) ? (xv - xt[d - D_]) : 0.f;
        der = fmaf(km, kick_v[p * D_ + d], der);
        split_store(g_abc_hi, g_abc_lo, base + d,           g0 * xv);
        split_store(g_abc_hi, g_abc_lo, base + D_ + d,      g1 * integ[d]);
        split_store(g_abc_hi, g_abc_lo, base + 2 * D_ + d,  g2 * der);
    }
}

__global__ void conv_w_kernel(const float* __restrict__ Wp,
                              const float* __restrict__ Wi,
                              const float* __restrict__ Wd)
{
    size_t i = (size_t)blockIdx.x * blockDim.x + threadIdx.x;
    if (i >= (size_t)3 * 1024 * K3) return;
    int k = (int)(i % K3);
    size_t pn = i / K3;
    int sel = k >> 10;
    const float* src = (sel == 0) ? Wp : (sel == 1) ? Wi : Wd;
    float v = src[pn * 1024 + (k & 1023)];
    split_store(g_w_hi, g_w_lo, i, v);
}

__global__ void conv_ow_kernel(const float* __restrict__ ow)
{
    size_t i = (size_t)blockIdx.x * blockDim.x + threadIdx.x;
    if (i >= (size_t)1024 * 1024) return;
    split_store(g_ow_hi, g_ow_lo, i, ow[i]);
}

// ============================ bf16x3 mma.sync GEMM ============================
// C[M x 1024] = sum over 3 terms: Ah*Bh^T + Al*Bh^T + Ah*Bl^T
// Layouts: A [row][k] (k contiguous), B = W [n][k] (k contiguous).
// CTA tile 128x128, K-chunk 32, 4-stage cp.async pipeline, 256 threads (8 warps 4x2).
#define KT      32
#define GSTG    4
#define ROWB    80                     // padded row bytes (64 data + 16 pad): conflict-free ldmatrix
#define ATILE_SZ (128 * ROWB)          // 10240
#define STAGE_SZ (2 * ATILE_SZ)        // 20480
#define GEMM_SMEM (GSTG * STAGE_SZ)    // 81920

struct GArgs {
    const __nv_bfloat16 *Ah, *Al, *Bh, *Bl;
    int K;        // per-term K
    int kpt;      // K / 32
};

__device__ __forceinline__ void gemm_issue(const GArgs& ga, uint32_t sb, int tid,
                                           int kc, int m0, int brow0)
{
    int term = kc / ga.kpt;
    int kk = (kc - term * ga.kpt) * KT;
    const __nv_bfloat16* As = (term == 1) ? ga.Al : ga.Ah;
    const __nv_bfloat16* Bs = (term == 2) ? ga.Bl : ga.Bh;
    uint32_t st = sb + (kc & (GSTG - 1)) * STAGE_SZ;
#pragma unroll
    for (int j = 0; j < 4; j++) {
        int i = tid + j * 256;             // 0..1023
        bool isB = (i >= 512);
        int idx = i & 511;
        int row = idx >> 2, c = idx & 3;
        const __nv_bfloat16* src = (isB ? Bs + (size_t)(brow0 + row) * ga.K
                                        : As + (size_t)(m0 + row) * ga.K) + kk + c * 8;
        uint32_t dst = st + (isB ? ATILE_SZ : 0) + row * ROWB + c * 16;
        cp_async16(dst, src);
    }
    cp_commit();
}

__global__ void __launch_bounds__(256, 1)
gemm_bf16x3(const __nv_bfloat16* __restrict__ Ah, const __nv_bfloat16* __restrict__ Al,
            const __nv_bfloat16* __restrict__ Bh, const __nv_bfloat16* __restrict__ Bl,
            float* c0, float* c1, float* c2, int kpt, int K)
{
    extern __shared__ __align__(256) char smem[];
    uint32_t sb = s2u(smem);
    int tid = threadIdx.x, lane = tid & 31, wid = tid >> 5;
    int wm = wid >> 1, wn = wid & 1;
    int by = blockIdx.y, bx = blockIdx.x;
    int proj = by >> 5;
    int m0 = by * 128;                     // A global row base (contiguous across projs)
    int brow0 = proj * 1024 + bx * 128;    // B (weight) row base
    GArgs ga{Ah, Al, Bh, Bl, K, kpt};
    int NC = 3 * kpt;

    float d[2][8][4];
#pragma unroll
    for (int i = 0; i < 2; i++)
#pragma unroll
        for (int j = 0; j < 8; j++)
#pragma unroll
            for (int q = 0; q < 4; q++) d[i][j][q] = 0.f;

    // per-lane ldmatrix offsets (within a stage)
    uint32_t a_off = (uint32_t)((wm * 32 + (lane & 15)) * ROWB + (lane >> 4) * 16);
    uint32_t b_off = (uint32_t)(ATILE_SZ
                     + (wn * 64 + ((lane >> 4) << 3) + (lane & 7)) * ROWB
                     + ((lane >> 3) & 1) * 16);

    // prologue: 3 stages
    gemm_issue(ga, sb, tid, 0, m0, brow0);
    gemm_issue(ga, sb, tid, 1, m0, brow0);
    gemm_issue(ga, sb, tid, 2, m0, brow0);

    for (int kc = 0; kc < NC; kc++) {
        if (kc + 3 < NC) gemm_issue(ga, sb, tid, kc + 3, m0, brow0);
        else cp_commit();
        cp_wait3();
        __syncthreads();
        uint32_t st = sb + (kc & (GSTG - 1)) * STAGE_SZ;
#pragma unroll
        for (int ks = 0; ks < 2; ks++) {
            uint32_t a0 = st + a_off + ks * 32;
            uint32_t ab = st + b_off + ks * 32;
            uint32_t a[2][4];
            ldsm_x4(a[0], a0);
            ldsm_x4(a[1], a0 + 16 * ROWB);
#pragma unroll
            for (int nt2 = 0; nt2 < 4; nt2++) {
                uint32_t b[4];
                ldsm_x4(b, ab + nt2 * 16 * ROWB);
                mma_bf16(d[0][2 * nt2],     a[0], b);
                mma_bf16(d[0][2 * nt2 + 1], a[0], b + 2);
                mma_bf16(d[1][2 * nt2],     a[1], b);
                mma_bf16(d[1][2 * nt2 + 1], a[1], b + 2);
            }
        }
        __syncthreads();
    }

    // epilogue
    float* C = (proj == 0) ? c0 : (proj == 1) ? c1 : c2;
    int g = lane >> 2, q = lane & 3;
    int rb = (by & 31) * 128 + wm * 32;
    int cb = bx * 128 + wn * 64;
#pragma unroll
    for (int mt = 0; mt < 2; mt++) {
#pragma unroll
        for (int nt = 0; nt < 8; nt++) {
            float* cp = C + (size_t)(rb + mt * 16 + g) * 1024 + cb + nt * 8 + q * 2;
            *(float2*)cp = make_float2(d[mt][nt][0], d[mt][nt][1]);
            *(float2*)(cp + 8 * 1024) = make_float2(d[mt][nt][2], d[mt][nt][3]);
        }
    }
}

// ============================ sparse attention ============================
template<int AA>
__global__ void attn_kernel(const int* __restrict__ positions)
{
    int wid = (blockIdx.x * blockDim.x + threadIdx.x) >> 5;
    int lane = threadIdx.x & 31;
    if (wid >= B_ * H_ * T_) return;
    int t = wid % T_;
    int h = (wid / T_) % H_;
    int b = wid / (T_ * H_);

    const float* qp = g_q + ((size_t)b * T_ + t) * D_ + h * DH_;
    int d0 = lane * 2;
    float q0 = qp[d0], q1 = qp[d0 + 1];

    int nv = 1 + min(3, t);
    if (t >= 4) nv += (31 - __clz((unsigned)t)) - 1;

    float sc[AA];
    int ps[AA];
    float mx = -1e30f;
#pragma unroll
    for (int a = 0; a < AA; a++) {
        int pos = positions[t * AA + a];
        ps[a] = pos;
        const float* kp = g_k + ((size_t)b * T_ + pos) * D_ + h * DH_;
        float s = fmaf(q0, kp[d0], q1 * kp[d0 + 1]);
#pragma unroll
        for (int o = 16; o; o >>= 1) s += __shfl_xor_sync(0xffffffffu, s, o);
        s = (a < nv) ? s * 0.125f : -1e30f;
        sc[a] = s;
        mx = fmaxf(mx, s);
    }
    float sum = 0.f;
#pragma unroll
    for (int a = 0; a < AA; a++) { sc[a] = expf(sc[a] - mx); sum += sc[a]; }
    float inv = 1.f / sum;
    float o0 = 0.f, o1 = 0.f;
#pragma unroll
    for (int a = 0; a < AA; a++) {
        const float* vp = g_v + ((size_t)b * T_ + ps[a]) * D_ + h * DH_;
        float wgt = sc[a] * inv;
        o0 = fmaf(wgt, vp[d0], o0);
        o1 = fmaf(wgt, vp[d0 + 1], o1);
    }
    size_t oi = ((size_t)b * T_ + t) * D_ + h * DH_ + d0;
    split_store(g_att_hi, g_att_lo, oi, o0);
    split_store(g_att_hi, g_att_lo, oi + 1, o1);
}

__global__ void attn_kernel_dyn(const int* __restrict__ positions, int A)
{
    int wid = (blockIdx.x * blockDim.x + threadIdx.x) >> 5;
    int lane = threadIdx.x & 31;
    if (wid >= B_ * H_ * T_) return;
    int t = wid % T_;
    int h = (wid / T_) % H_;
    int b = wid / (T_ * H_);
    const float* qp = g_q + ((size_t)b * T_ + t) * D_ + h * DH_;
    int d0 = lane * 2;
    float q0 = qp[d0], q1 = qp[d0 + 1];
    int nv = 1 + min(3, t);
    if (t >= 4) nv += (31 - __clz((unsigned)t)) - 1;
    float sc[32]; int ps[32];
    float mx = -1e30f;
    for (int a = 0; a < A; a++) {
        int pos = positions[t * A + a];
        ps[a] = pos;
        const float* kp = g_k + ((size_t)b * T_ + pos) * D_ + h * DH_;
        float s = fmaf(q0, kp[d0], q1 * kp[d0 + 1]);
        for (int o = 16; o; o >>= 1) s += __shfl_xor_sync(0xffffffffu, s, o);
        s = (a < nv) ? s * 0.125f : -1e30f;
        sc[a] = s; mx = fmaxf(mx, s);
    }
    float sum = 0.f;
    for (int a = 0; a < A; a++) { sc[a] = expf(sc[a] - mx); sum += sc[a]; }
    float inv = 1.f / sum;
    float o0 = 0.f, o1 = 0.f;
    for (int a = 0; a < A; a++) {
        const float* vp = g_v + ((size_t)b * T_ + ps[a]) * D_ + h * DH_;
        float wgt = sc[a] * inv;
        o0 = fmaf(wgt, vp[d0], o0);
        o1 = fmaf(wgt, vp[d0 + 1], o1);
    }
    size_t oi = ((size_t)b * T_ + t) * D_ + h * DH_ + d0;
    split_store(g_att_hi, g_att_lo, oi, o0);
    split_store(g_att_hi, g_att_lo, oi + 1, o1);
}

// ============================ launcher ============================
extern "C" void kernel_launch(void* const* d_in, const int* in_sizes, int n_in,
                              void* d_out, int out_size)
{
    const float* x       = (const float*)d_in[0];
    const float* qkv_Wp  = (const float*)d_in[1];
    const float* qkv_Wi  = (const float*)d_in[2];
    const float* qkv_Wd  = (const float*)d_in[3];
    const float* gate_w  = (const float*)d_in[4];
    const float* gate_b  = (const float*)d_in[5];
    const float* kick_v  = (const float*)d_in[6];
    const float* kick_w  = (const float*)d_in[7];
    const float* kick_b  = (const float*)d_in[8];
    const float* o_w     = (const float*)d_in[9];
    const int*   positions = (const int*)d_in[10];
    int A = in_sizes[10] / T_;

    float* out = (float*)d_out;

    void *p_abc_hi, *p_abc_lo, *p_w_hi, *p_w_lo, *p_ow_hi, *p_ow_lo;
    void *p_q, *p_k, *p_v, *p_att_hi, *p_att_lo;
    cudaGetSymbolAddress(&p_abc_hi, g_abc_hi);
    cudaGetSymbolAddress(&p_abc_lo, g_abc_lo);
    cudaGetSymbolAddress(&p_w_hi, g_w_hi);
    cudaGetSymbolAddress(&p_w_lo, g_w_lo);
    cudaGetSymbolAddress(&p_ow_hi, g_ow_hi);
    cudaGetSymbolAddress(&p_ow_lo, g_ow_lo);
    cudaGetSymbolAddress(&p_q, g_q);
    cudaGetSymbolAddress(&p_k, g_k);
    cudaGetSymbolAddress(&p_v, g_v);
    cudaGetSymbolAddress(&p_att_hi, g_att_hi);
    cudaGetSymbolAddress(&p_att_lo, g_att_lo);

    cudaFuncSetAttribute(gemm_bf16x3, cudaFuncAttributeMaxDynamicSharedMemorySize, GEMM_SMEM);

    // 1. per-token gates / kick / stagnation
    token_stats_kernel<<<NTOK, 128>>>(x, gate_w, gate_b, kick_w, kick_b);
    // 2. EMA integral
    ema_kernel<<<(B_ * D_ + 255) / 256, 256>>>(x);
    // 3. weight hi/lo conversion
    conv_w_kernel<<<(3 * 1024 * K3 + 255) / 256, 256>>>(qkv_Wp, qkv_Wi, qkv_Wd);
    conv_ow_kernel<<<(1024 * 1024 + 255) / 256, 256>>>(o_w);
    // 4. gated GEMM inputs (hi/lo bf16) for all 3 projections
    dim3 gb(NTOK, 3);
    build_abc_kernel<<<gb, 256>>>(x, kick_v);
    // 5. projection GEMMs: grid (1024/128, 3*4096/128) = (8, 96)
    dim3 pgrid(1024 / 128, 3 * (NTOK / 128));
    gemm_bf16x3<<<pgrid, 256, GEMM_SMEM>>>(
        (const __nv_bfloat16*)p_abc_hi, (const __nv_bfloat16*)p_abc_lo,
        (const __nv_bfloat16*)p_w_hi, (const __nv_bfloat16*)p_w_lo,
        (float*)p_q, (float*)p_k, (float*)p_v, K3 / KT, K3);
    // 6. sparse dilated attention
    int nwarps = B_ * H_ * T_;
    int nblocks = nwarps / 4;
    if (A == 15)
        attn_kernel<15><<<nblocks, 128>>>(positions);
    else
        attn_kernel_dyn<<<nblocks, 128>>>(positions, A);
    // 7. output projection: grid (8, 32)
    dim3 ogrid(1024 / 128, NTOK / 128);
    gemm_bf16x3<<<ogrid, 256, GEMM_SMEM>>>(
        (const __nv_bfloat16*)p_att_hi, (const __nv_bfloat16*)p_att_lo,
        (const __nv_bfloat16*)p_ow_hi, (const __nv_bfloat16*)p_ow_lo,
        out, out, out, D_ / KT, D_);
}

// round 4
// speedup vs baseline: 2.5319x; 1.6647x over previous
#include <cuda_runtime.h>
#include <cuda_bf16.h>
#include <math.h>
#include <stdint.h>

#define B_  2
#define T_  2048
#define D_  1024
#define H_  16
#define DH_ 64
#define NTOK (B_*T_)          // 4096
#define K3  3072

// ---------------- scratch (device globals; no allocation) ----------------
__device__ __align__(256) float g_integral[(size_t)NTOK * D_];
__device__ float g_params[(size_t)NTOK * 12];
__device__ __align__(256) __nv_bfloat16 g_abc_hi[(size_t)3 * NTOK * K3];
__device__ __align__(256) __nv_bfloat16 g_abc_lo[(size_t)3 * NTOK * K3];
__device__ __align__(256) __nv_bfloat16 g_w_hi[(size_t)3 * 1024 * K3];
__device__ __align__(256) __nv_bfloat16 g_w_lo[(size_t)3 * 1024 * K3];
__device__ __align__(256) __nv_bfloat16 g_ow_hi[(size_t)1024 * 1024];
__device__ __align__(256) __nv_bfloat16 g_ow_lo[(size_t)1024 * 1024];
__device__ __align__(256) float g_q[(size_t)NTOK * D_];
__device__ __align__(256) float g_k[(size_t)NTOK * D_];
__device__ __align__(256) float g_v[(size_t)NTOK * D_];
__device__ __align__(256) __nv_bfloat16 g_att_hi[(size_t)NTOK * D_];
__device__ __align__(256) __nv_bfloat16 g_att_lo[(size_t)NTOK * D_];

// ============================ PTX helpers (sm_100-baseline safe) ============================
__device__ __forceinline__ uint32_t s2u(const void* p) {
    uint32_t a;
    asm("{ .reg .u64 t; cvta.to.shared.u64 t, %1; cvt.u32.u64 %0, t; }" : "=r"(a) : "l"(p));
    return a;
}
__device__ __forceinline__ void cp_async16(uint32_t dst, const void* src) {
    asm volatile("cp.async.cg.shared.global [%0], [%1], 16;" :: "r"(dst), "l"(src));
}
__device__ __forceinline__ void cp_commit() {
    asm volatile("cp.async.commit_group;" ::: "memory");
}
__device__ __forceinline__ void cp_wait2() {
    asm volatile("cp.async.wait_group 2;" ::: "memory");
}
__device__ __forceinline__ void ldsm_x4(uint32_t* r, uint32_t addr) {
    asm volatile("ldmatrix.sync.aligned.m8n8.x4.shared.b16 {%0,%1,%2,%3}, [%4];"
        : "=r"(r[0]), "=r"(r[1]), "=r"(r[2]), "=r"(r[3]) : "r"(addr));
}
__device__ __forceinline__ void mma_bf16(float* d, const uint32_t* a, const uint32_t* b) {
    asm volatile(
        "mma.sync.aligned.m16n8k16.row.col.f32.bf16.bf16.f32 "
        "{%0,%1,%2,%3}, {%4,%5,%6,%7}, {%8,%9}, {%0,%1,%2,%3};"
        : "+f"(d[0]), "+f"(d[1]), "+f"(d[2]), "+f"(d[3])
        : "r"(a[0]), "r"(a[1]), "r"(a[2]), "r"(a[3]), "r"(b[0]), "r"(b[1]));
}

// ============================ misc kernels ============================
__global__ void token_stats_kernel(const float* __restrict__ x,
                                   const float* __restrict__ gate_w,
                                   const float* __restrict__ gate_b,
                                   const float* __restrict__ kick_w,
                                   const float* __restrict__ kick_b)
{
    int r = blockIdx.x;
    int t = r % T_;
    const float* xt = x + (size_t)r * D_;
    int tid = threadIdx.x;

    float acc[15];
#pragma unroll
    for (int v = 0; v < 15; v++) acc[v] = 0.f;

    for (int d = tid; d < D_; d += 128) {
        float xv = xt[d];
        float pv = (t > 0) ? xt[d - D_] : 0.f;
        acc[0] = fmaf(xv, xv, acc[0]);
        acc[1] = fmaf(xv, pv, acc[1]);
        acc[2] = fmaf(pv, pv, acc[2]);
        acc[3] = fmaf(xv, kick_w[0 * D_ + d], acc[3]);
        acc[4] = fmaf(xv, kick_w[1 * D_ + d], acc[4]);
        acc[5] = fmaf(xv, kick_w[2 * D_ + d], acc[5]);
#pragma unroll
        for (int j = 0; j < 9; j++)
            acc[6 + j] = fmaf(xv, gate_w[j * D_ + d], acc[6 + j]);
    }
#pragma unroll
    for (int v = 0; v < 15; v++)
#pragma unroll
        for (int off = 16; off; off >>= 1)
            acc[v] += __shfl_down_sync(0xffffffffu, acc[v], off);

    __shared__ float red[15][4];
    int w = tid >> 5, l = tid & 31;
    if (l == 0)
#pragma unroll
        for (int v = 0; v < 15; v++) red[v][w] = acc[v];
    __syncthreads();

    if (tid == 0) {
        float s[15];
#pragma unroll
        for (int v = 0; v < 15; v++)
            s[v] = red[v][0] + red[v][1] + red[v][2] + red[v][3];
        float nt = fmaxf(sqrtf(s[0]), 1e-12f);
        float np = fmaxf(sqrtf(s[2]), 1e-12f);
        float cosv = (t > 0) ? s[1] / (nt * np) : 0.f;
        float stag = (cosv > 0.95f) ? 1.f : 0.f;
        float* out = g_params + (size_t)r * 12;
#pragma unroll
        for (int p = 0; p < 3; p++) {
            float ks = 1.f / (1.f + expf(-(s[3 + p] + kick_b[p])));
            float l0 = s[6 + p * 3 + 0] + gate_b[p * 3 + 0];
            float l1 = s[6 + p * 3 + 1] + gate_b[p * 3 + 1];
            float l2 = s[6 + p * 3 + 2] + gate_b[p * 3 + 2];
            float m = fmaxf(l0, fmaxf(l1, l2));
            float e0 = expf(l0 - m), e1 = expf(l1 - m), e2 = expf(l2 - m);
            float inv = 1.f / (e0 + e1 + e2);
            float g0 = fminf(e0 * inv, 0.6f);
            float g1 = fminf(e1 * inv, 0.6f);
            float g2 = fminf(e2 * inv, 0.6f);
            g1 = fmaxf(g1, 0.25f);
            float gi = 1.f / (g0 + g1 + g2);
            out[p * 4 + 0] = g0 * gi;
            out[p * 4 + 1] = g1 * gi;
            out[p * 4 + 2] = g2 * gi;
            out[p * 4 + 3] = stag * ks;
        }
    }
}

__global__ void ema_kernel(const float* __restrict__ x)
{
    int c = blockIdx.x * blockDim.x + threadIdx.x;
    if (c >= B_ * D_) return;
    int b = c / D_, d = c % D_;
    const float* xp = x + (size_t)b * T_ * D_ + d;
    float* ip = g_integral + (size_t)b * T_ * D_ + d;
    float acc = xp[0];
    ip[0] = acc;
#pragma unroll 8
    for (int t = 1; t < T_; t++) {
        acc = fmaf(0.95f, acc, 0.05f * xp[(size_t)t * D_]);
        ip[(size_t)t * D_] = acc;
    }
}

// pack two fp32 into hi/lo bf16 pairs and store as 4B each
__device__ __forceinline__ void split_store2(__nv_bfloat16* hi, __nv_bfloat16* lo,
                                             size_t idx, float v0, float v1) {
    __nv_bfloat16 h0 = __float2bfloat16(v0);
    __nv_bfloat16 h1 = __float2bfloat16(v1);
    __nv_bfloat16 l0 = __float2bfloat16(v0 - __bfloat162float(h0));
    __nv_bfloat16 l1 = __float2bfloat16(v1 - __bfloat162float(h1));
    __nv_bfloat162 hp; hp.x = h0; hp.y = h1;
    __nv_bfloat162 lp; lp.x = l0; lp.y = l1;
    *(__nv_bfloat162*)(hi + idx) = hp;
    *(__nv_bfloat162*)(lo + idx) = lp;
}

__global__ void build_abc_kernel(const float* __restrict__ x,
                                 const float* __restrict__ kick_v)
{
    int r = blockIdx.x;
    int p = blockIdx.y;
    int t = r % T_;
    const float* par = g_params + (size_t)r * 12 + p * 4;
    float g0 = par[0], g1 = par[1], g2 = par[2], km = par[3];
    size_t base = ((size_t)p * NTOK + r) * K3;
    const float* xt = x + (size_t)r * D_;
    const float* integ = g_integral + (size_t)r * D_;
    for (int d2 = threadIdx.x; d2 < D_ / 2; d2 += blockDim.x) {
        int d = d2 * 2;
        float2 xv = *(const float2*)(xt + d);
        float2 iv = *(const float2*)(integ + d);
        float der0, der1;
        if (t > 0) {
            float2 pv = *(const float2*)(xt + d - D_);
            der0 = xv.x - pv.x; der1 = xv.y - pv.y;
        } else { der0 = 0.f; der1 = 0.f; }
        float2 kv = *(const float2*)(kick_v + p * D_ + d);
        der0 = fmaf(km, kv.x, der0);
        der1 = fmaf(km, kv.y, der1);
        split_store2(g_abc_hi, g_abc_lo, base + d,          g0 * xv.x, g0 * xv.y);
        split_store2(g_abc_hi, g_abc_lo, base + D_ + d,     g1 * iv.x, g1 * iv.y);
        split_store2(g_abc_hi, g_abc_lo, base + 2 * D_ + d, g2 * der0, g2 * der1);
    }
}

__global__ void conv_w_kernel(const float* __restrict__ Wp,
                              const float* __restrict__ Wi,
                              const float* __restrict__ Wd)
{
    size_t i2 = (size_t)blockIdx.x * blockDim.x + threadIdx.x;
    if (i2 >= (size_t)3 * 1024 * K3 / 2) return;
    size_t i = i2 * 2;
    int k = (int)(i % K3);
    size_t pn = i / K3;
    int sel = k >> 10;
    const float* src = (sel == 0) ? Wp : (sel == 1) ? Wi : Wd;
    float2 v = *(const float2*)(src + pn * 1024 + (k & 1023));
    split_store2(g_w_hi, g_w_lo, i, v.x, v.y);
}

__global__ void conv_ow_kernel(const float* __restrict__ ow)
{
    size_t i2 = (size_t)blockIdx.x * blockDim.x + threadIdx.x;
    if (i2 >= (size_t)1024 * 1024 / 2) return;
    size_t i = i2 * 2;
    float2 v = *(const float2*)(ow + i);
    split_store2(g_ow_hi, g_ow_lo, i, v.x, v.y);
}

// ============================ bf16x3 mma.sync GEMM v2 ============================
// C[M x 1024] = Ah*Bh^T + Al*Bh^T + Ah*Bl^T   (A [m][k], B=W [n][k], both k-contiguous)
// CTA tile 128x128, K-chunk 64, 4-stage cp.async, one __syncthreads per chunk.
#define KT      64
#define GSTG    4
#define ROWB    144                    // 128B data + 16B skew: conflict-free ldmatrix
#define ATILE_SZ (128 * ROWB)          // 18432
#define STAGE_SZ (2 * ATILE_SZ)        // 36864
#define GEMM_SMEM (GSTG * STAGE_SZ)    // 147456

__device__ __forceinline__ void gemm_issue(
    const __nv_bfloat16* As, const __nv_bfloat16* Bs, int K,
    uint32_t sb, int tid, int stage, int kk, int m0, int brow0)
{
    uint32_t st = sb + stage * STAGE_SZ;
#pragma unroll
    for (int j = 0; j < 8; j++) {
        int i = tid + j * 256;             // 0..2047
        bool isB = (i >= 1024);
        int idx = i & 1023;
        int row = idx >> 3, c = idx & 7;   // 8 x 16B = 128B per row
        const __nv_bfloat16* src = (isB ? Bs + (size_t)(brow0 + row) * K
                                        : As + (size_t)(m0 + row) * K) + kk + c * 8;
        uint32_t dst = st + (isB ? ATILE_SZ : 0) + row * ROWB + c * 16;
        cp_async16(dst, src);
    }
    cp_commit();
}

__global__ void __launch_bounds__(256, 1)
gemm_bf16x3(const __nv_bfloat16* __restrict__ Ah, const __nv_bfloat16* __restrict__ Al,
            const __nv_bfloat16* __restrict__ Bh, const __nv_bfloat16* __restrict__ Bl,
            float* c0, float* c1, float* c2, int kpt, int K)
{
    extern __shared__ __align__(256) char smem[];
    uint32_t sb = s2u(smem);
    int tid = threadIdx.x, lane = tid & 31, wid = tid >> 5;
    int wm = wid >> 1, wn = wid & 1;
    int by = blockIdx.y, bx = blockIdx.x;
    int proj = by >> 5;
    int m0 = by * 128;
    int brow0 = proj * 1024 + bx * 128;
    int NC = 3 * kpt;

    float d[2][8][4];
#pragma unroll
    for (int i = 0; i < 2; i++)
#pragma unroll
        for (int j = 0; j < 8; j++)
#pragma unroll
            for (int q = 0; q < 4; q++) d[i][j][q] = 0.f;

    uint32_t a_off = (uint32_t)((wm * 32 + (lane & 15)) * ROWB + (lane >> 4) * 16);
    uint32_t b_off = (uint32_t)(ATILE_SZ
                     + (wn * 64 + ((lane >> 4) << 3) + (lane & 7)) * ROWB
                     + ((lane >> 3) & 1) * 16);

    // producer counters (no division in the loop)
    int pterm = 0, pkc = 0;
    const __nv_bfloat16* pA = Ah;
    const __nv_bfloat16* pB = Bh;

    // prologue: 3 chunks
#pragma unroll
    for (int pr = 0; pr < 3; pr++) {
        gemm_issue(pA, pB, K, sb, tid, pr, pkc * KT, m0, brow0);
        if (++pkc == kpt) {
            pkc = 0; pterm++;
            pA = (pterm == 1) ? Al : Ah;
            pB = (pterm == 2) ? Bl : Bh;
        }
    }
    int pstage = 3;

    for (int kc = 0; kc < NC; kc++) {
        cp_wait2();
        __syncthreads();
        uint32_t st = sb + (kc & (GSTG - 1)) * STAGE_SZ;
#pragma unroll
        for (int ks = 0; ks < 4; ks++) {
            uint32_t a0 = st + a_off + ks * 32;
            uint32_t ab = st + b_off + ks * 32;
            uint32_t a[2][4];
            ldsm_x4(a[0], a0);
            ldsm_x4(a[1], a0 + 16 * ROWB);
#pragma unroll
            for (int nt2 = 0; nt2 < 4; nt2++) {
                uint32_t b[4];
                ldsm_x4(b, ab + nt2 * 16 * ROWB);
                mma_bf16(d[0][2 * nt2],     a[0], b);
                mma_bf16(d[0][2 * nt2 + 1], a[0], b + 2);
                mma_bf16(d[1][2 * nt2],     a[1], b);
                mma_bf16(d[1][2 * nt2 + 1], a[1], b + 2);
            }
        }
        // issue next chunk into stage (kc+3)&3 — its previous readers
        // were fenced by this iteration's entry __syncthreads
        if (pterm < 3) {
            gemm_issue(pA, pB, K, sb, tid, pstage, pkc * KT, m0, brow0);
            if (++pkc == kpt) {
                pkc = 0; pterm++;
                pA = (pterm == 1) ? Al : Ah;
                pB = (pterm == 2) ? Bl : Bh;
            }
            if (++pstage == GSTG) pstage = 0;
        } else {
            cp_commit();   // keep group accounting uniform
        }
    }

    // epilogue
    float* C = (proj == 0) ? c0 : (proj == 1) ? c1 : c2;
    int g = lane >> 2, q = lane & 3;
    int rb = (by & 31) * 128 + wm * 32;
    int cb = bx * 128 + wn * 64;
#pragma unroll
    for (int mt = 0; mt < 2; mt++) {
#pragma unroll
        for (int nt = 0; nt < 8; nt++) {
            float* cp = C + (size_t)(rb + mt * 16 + g) * 1024 + cb + nt * 8 + q * 2;
            *(float2*)cp = make_float2(d[mt][nt][0], d[mt][nt][1]);
            *(float2*)(cp + 8 * 1024) = make_float2(d[mt][nt][2], d[mt][nt][3]);
        }
    }
}

// ============================ sparse attention ============================
template<int AA>
__global__ void attn_kernel(const int* __restrict__ positions)
{
    int wid = (blockIdx.x * blockDim.x + threadIdx.x) >> 5;
    int lane = threadIdx.x & 31;
    if (wid >= B_ * H_ * T_) return;
    int t = wid % T_;
    int h = (wid / T_) % H_;
    int b = wid / (T_ * H_);

    const float* qp = g_q + ((size_t)b * T_ + t) * D_ + h * DH_;
    int d0 = lane * 2;
    float q0 = qp[d0], q1 = qp[d0 + 1];

    int nv = 1 + min(3, t);
    if (t >= 4) nv += (31 - __clz((unsigned)t)) - 1;

    float sc[AA];
    int ps[AA];
    float mx = -1e30f;
#pragma unroll
    for (int a = 0; a < AA; a++) {
        int pos = positions[t * AA + a];
        ps[a] = pos;
        const float* kp = g_k + ((size_t)b * T_ + pos) * D_ + h * DH_;
        float s = fmaf(q0, kp[d0], q1 * kp[d0 + 1]);
#pragma unroll
        for (int o = 16; o; o >>= 1) s += __shfl_xor_sync(0xffffffffu, s, o);
        s = (a < nv) ? s * 0.125f : -1e30f;
        sc[a] = s;
        mx = fmaxf(mx, s);
    }
    float sum = 0.f;
#pragma unroll
    for (int a = 0; a < AA; a++) { sc[a] = expf(sc[a] - mx); sum += sc[a]; }
    float inv = 1.f / sum;
    float o0 = 0.f, o1 = 0.f;
#pragma unroll
    for (int a = 0; a < AA; a++) {
        const float* vp = g_v + ((size_t)b * T_ + ps[a]) * D_ + h * DH_;
        float wgt = sc[a] * inv;
        o0 = fmaf(wgt, vp[d0], o0);
        o1 = fmaf(wgt, vp[d0 + 1], o1);
    }
    size_t oi = ((size_t)b * T_ + t) * D_ + h * DH_ + d0;
    split_store2(g_att_hi, g_att_lo, oi, o0, o1);
}

__global__ void attn_kernel_dyn(const int* __restrict__ positions, int A)
{
    int wid = (blockIdx.x * blockDim.x + threadIdx.x) >> 5;
    int lane = threadIdx.x & 31;
    if (wid >= B_ * H_ * T_) return;
    int t = wid % T_;
    int h = (wid / T_) % H_;
    int b = wid / (T_ * H_);
    const float* qp = g_q + ((size_t)b * T_ + t) * D_ + h * DH_;
    int d0 = lane * 2;
    float q0 = qp[d0], q1 = qp[d0 + 1];
    int nv = 1 + min(3, t);
    if (t >= 4) nv += (31 - __clz((unsigned)t)) - 1;
    float sc[32]; int ps[32];
    float mx = -1e30f;
    for (int a = 0; a < A; a++) {
        int pos = positions[t * A + a];
        ps[a] = pos;
        const float* kp = g_k + ((size_t)b * T_ + pos) * D_ + h * DH_;
        float s = fmaf(q0, kp[d0], q1 * kp[d0 + 1]);
        for (int o = 16; o; o >>= 1) s += __shfl_xor_sync(0xffffffffu, s, o);
        s = (a < nv) ? s * 0.125f : -1e30f;
        sc[a] = s; mx = fmaxf(mx, s);
    }
    float sum = 0.f;
    for (int a = 0; a < A; a++) { sc[a] = expf(sc[a] - mx); sum += sc[a]; }
    float inv = 1.f / sum;
    float o0 = 0.f, o1 = 0.f;
    for (int a = 0; a < A; a++) {
        const float* vp = g_v + ((size_t)b * T_ + ps[a]) * D_ + h * DH_;
        float wgt = sc[a] * inv;
        o0 = fmaf(wgt, vp[d0], o0);
        o1 = fmaf(wgt, vp[d0 + 1], o1);
    }
    size_t oi = ((size_t)b * T_ + t) * D_ + h * DH_ + d0;
    split_store2(g_att_hi, g_att_lo, oi, o0, o1);
}

// ============================ launcher ============================
extern "C" void kernel_launch(void* const* d_in, const int* in_sizes, int n_in,
                              void* d_out, int out_size)
{
    const float* x       = (const float*)d_in[0];
    const float* qkv_Wp  = (const float*)d_in[1];
    const float* qkv_Wi  = (const float*)d_in[2];
    const float* qkv_Wd  = (const float*)d_in[3];
    const float* gate_w  = (const float*)d_in[4];
    const float* gate_b  = (const float*)d_in[5];
    const float* kick_v  = (const float*)d_in[6];
    const float* kick_w  = (const float*)d_in[7];
    const float* kick_b  = (const float*)d_in[8];
    const float* o_w     = (const float*)d_in[9];
    const int*   positions = (const int*)d_in[10];
    int A = in_sizes[10] / T_;

    float* out = (float*)d_out;

    void *p_abc_hi, *p_abc_lo, *p_w_hi, *p_w_lo, *p_ow_hi, *p_ow_lo;
    void *p_q, *p_k, *p_v, *p_att_hi, *p_att_lo;
    cudaGetSymbolAddress(&p_abc_hi, g_abc_hi);
    cudaGetSymbolAddress(&p_abc_lo, g_abc_lo);
    cudaGetSymbolAddress(&p_w_hi, g_w_hi);
    cudaGetSymbolAddress(&p_w_lo, g_w_lo);
    cudaGetSymbolAddress(&p_ow_hi, g_ow_hi);
    cudaGetSymbolAddress(&p_ow_lo, g_ow_lo);
    cudaGetSymbolAddress(&p_q, g_q);
    cudaGetSymbolAddress(&p_k, g_k);
    cudaGetSymbolAddress(&p_v, g_v);
    cudaGetSymbolAddress(&p_att_hi, g_att_hi);
    cudaGetSymbolAddress(&p_att_lo, g_att_lo);

    cudaFuncSetAttribute(gemm_bf16x3, cudaFuncAttributeMaxDynamicSharedMemorySize, GEMM_SMEM);

    // 1. per-token gates / kick / stagnation
    token_stats_kernel<<<NTOK, 128>>>(x, gate_w, gate_b, kick_w, kick_b);
    // 2. EMA integral
    ema_kernel<<<(B_ * D_ + 255) / 256, 256>>>(x);
    // 3. weight hi/lo conversion (vectorized x2)
    conv_w_kernel<<<(3 * 1024 * K3 / 2 + 255) / 256, 256>>>(qkv_Wp, qkv_Wi, qkv_Wd);
    conv_ow_kernel<<<(1024 * 1024 / 2 + 255) / 256, 256>>>(o_w);
    // 4. gated GEMM inputs (hi/lo bf16)
    dim3 gb(NTOK, 3);
    build_abc_kernel<<<gb, 256>>>(x, kick_v);
    // 5. projection GEMMs: grid (8, 96)
    dim3 pgrid(1024 / 128, 3 * (NTOK / 128));
    gemm_bf16x3<<<pgrid, 256, GEMM_SMEM>>>(
        (const __nv_bfloat16*)p_abc_hi, (const __nv_bfloat16*)p_abc_lo,
        (const __nv_bfloat16*)p_w_hi, (const __nv_bfloat16*)p_w_lo,
        (float*)p_q, (float*)p_k, (float*)p_v, K3 / KT, K3);
    // 6. sparse dilated attention
    int nwarps = B_ * H_ * T_;
    int nblocks = nwarps / 4;
    if (A == 15)
        attn_kernel<15><<<nblocks, 128>>>(positions);
    else
        attn_kernel_dyn<<<nblocks, 128>>>(positions, A);
    // 7. output projection: grid (8, 32)
    dim3 ogrid(1024 / 128, NTOK / 128);
    gemm_bf16x3<<<ogrid, 256, GEMM_SMEM>>>(
        (const __nv_bfloat16*)p_att_hi, (const __nv_bfloat16*)p_att_lo,
        (const __nv_bfloat16*)p_ow_hi, (const __nv_bfloat16*)p_ow_lo,
        out, out, out, D_ / KT, D_);
}

// round 5
// speedup vs baseline: 2.8101x; 1.1099x over previous
#include <cuda_runtime.h>
#include <cuda_bf16.h>
#include <math.h>
#include <stdint.h>

#define B_  2
#define T_  2048
#define D_  1024
#define H_  16
#define DH_ 64
#define NTOK (B_*T_)          // 4096
#define K3  3072

// ---------------- scratch (device globals; no allocation) ----------------
__device__ __align__(256) float g_integral[(size_t)NTOK * D_];
__device__ float g_params[(size_t)NTOK * 12];
__device__ __align__(256) __nv_bfloat16 g_abc_hi[(size_t)3 * NTOK * K3];
__device__ __align__(256) __nv_bfloat16 g_abc_lo[(size_t)3 * NTOK * K3];
__device__ __align__(256) __nv_bfloat16 g_w_hi[(size_t)3 * 1024 * K3];
__device__ __align__(256) __nv_bfloat16 g_w_lo[(size_t)3 * 1024 * K3];
__device__ __align__(256) __nv_bfloat16 g_ow_hi[(size_t)1024 * 1024];
__device__ __align__(256) __nv_bfloat16 g_ow_lo[(size_t)1024 * 1024];
__device__ __align__(256) float g_q[(size_t)NTOK * D_];
__device__ __align__(256) float g_k[(size_t)NTOK * D_];
__device__ __align__(256) float g_v[(size_t)NTOK * D_];
__device__ __align__(256) __nv_bfloat16 g_att_hi[(size_t)NTOK * D_];
__device__ __align__(256) __nv_bfloat16 g_att_lo[(size_t)NTOK * D_];

// ============================ PTX helpers (sm_100-baseline safe) ============================
__device__ __forceinline__ uint32_t s2u(const void* p) {
    uint32_t a;
    asm("{ .reg .u64 t; cvta.to.shared.u64 t, %1; cvt.u32.u64 %0, t; }" : "=r"(a) : "l"(p));
    return a;
}
__device__ __forceinline__ void cp_async16(uint32_t dst, const void* src) {
    asm volatile("cp.async.cg.shared.global [%0], [%1], 16;" :: "r"(dst), "l"(src));
}
__device__ __forceinline__ void cp_commit() {
    asm volatile("cp.async.commit_group;" ::: "memory");
}
__device__ __forceinline__ void cp_wait1() {
    asm volatile("cp.async.wait_group 1;" ::: "memory");
}
__device__ __forceinline__ void ldsm_x4(uint32_t* r, uint32_t addr) {
    asm volatile("ldmatrix.sync.aligned.m8n8.x4.shared.b16 {%0,%1,%2,%3}, [%4];"
        : "=r"(r[0]), "=r"(r[1]), "=r"(r[2]), "=r"(r[3]) : "r"(addr));
}
__device__ __forceinline__ void mma_bf16(float* d, const uint32_t* a, const uint32_t* b) {
    asm volatile(
        "mma.sync.aligned.m16n8k16.row.col.f32.bf16.bf16.f32 "
        "{%0,%1,%2,%3}, {%4,%5,%6,%7}, {%8,%9}, {%0,%1,%2,%3};"
        : "+f"(d[0]), "+f"(d[1]), "+f"(d[2]), "+f"(d[3])
        : "r"(a[0]), "r"(a[1]), "r"(a[2]), "r"(a[3]), "r"(b[0]), "r"(b[1]));
}

// ============================ misc kernels ============================
__global__ void token_stats_kernel(const float* __restrict__ x,
                                   const float* __restrict__ gate_w,
                                   const float* __restrict__ gate_b,
                                   const float* __restrict__ kick_w,
                                   const float* __restrict__ kick_b)
{
    int r = blockIdx.x;
    int t = r % T_;
    const float* xt = x + (size_t)r * D_;
    int tid = threadIdx.x;

    float acc[15];
#pragma unroll
    for (int v = 0; v < 15; v++) acc[v] = 0.f;

    for (int d = tid; d < D_; d += 128) {
        float xv = xt[d];
        float pv = (t > 0) ? xt[d - D_] : 0.f;
        acc[0] = fmaf(xv, xv, acc[0]);
        acc[1] = fmaf(xv, pv, acc[1]);
        acc[2] = fmaf(pv, pv, acc[2]);
        acc[3] = fmaf(xv, kick_w[0 * D_ + d], acc[3]);
        acc[4] = fmaf(xv, kick_w[1 * D_ + d], acc[4]);
        acc[5] = fmaf(xv, kick_w[2 * D_ + d], acc[5]);
#pragma unroll
        for (int j = 0; j < 9; j++)
            acc[6 + j] = fmaf(xv, gate_w[j * D_ + d], acc[6 + j]);
    }
#pragma unroll
    for (int v = 0; v < 15; v++)
#pragma unroll
        for (int off = 16; off; off >>= 1)
            acc[v] += __shfl_down_sync(0xffffffffu, acc[v], off);

    __shared__ float red[15][4];
    int w = tid >> 5, l = tid & 31;
    if (l == 0)
#pragma unroll
        for (int v = 0; v < 15; v++) red[v][w] = acc[v];
    __syncthreads();

    if (tid == 0) {
        float s[15];
#pragma unroll
        for (int v = 0; v < 15; v++)
            s[v] = red[v][0] + red[v][1] + red[v][2] + red[v][3];
        float nt = fmaxf(sqrtf(s[0]), 1e-12f);
        float np = fmaxf(sqrtf(s[2]), 1e-12f);
        float cosv = (t > 0) ? s[1] / (nt * np) : 0.f;
        float stag = (cosv > 0.95f) ? 1.f : 0.f;
        float* out = g_params + (size_t)r * 12;
#pragma unroll
        for (int p = 0; p < 3; p++) {
            float ks = 1.f / (1.f + expf(-(s[3 + p] + kick_b[p])));
            float l0 = s[6 + p * 3 + 0] + gate_b[p * 3 + 0];
            float l1 = s[6 + p * 3 + 1] + gate_b[p * 3 + 1];
            float l2 = s[6 + p * 3 + 2] + gate_b[p * 3 + 2];
            float m = fmaxf(l0, fmaxf(l1, l2));
            float e0 = expf(l0 - m), e1 = expf(l1 - m), e2 = expf(l2 - m);
            float inv = 1.f / (e0 + e1 + e2);
            float g0 = fminf(e0 * inv, 0.6f);
            float g1 = fminf(e1 * inv, 0.6f);
            float g2 = fminf(e2 * inv, 0.6f);
            g1 = fmaxf(g1, 0.25f);
            float gi = 1.f / (g0 + g1 + g2);
            out[p * 4 + 0] = g0 * gi;
            out[p * 4 + 1] = g1 * gi;
            out[p * 4 + 2] = g2 * gi;
            out[p * 4 + 3] = stag * ks;
        }
    }
}

__global__ void ema_kernel(const float* __restrict__ x)
{
    int c = blockIdx.x * blockDim.x + threadIdx.x;
    if (c >= B_ * D_) return;
    int b = c / D_, d = c % D_;
    const float* xp = x + (size_t)b * T_ * D_ + d;
    float* ip = g_integral + (size_t)b * T_ * D_ + d;
    float acc = xp[0];
    ip[0] = acc;
#pragma unroll 8
    for (int t = 1; t < T_; t++) {
        acc = fmaf(0.95f, acc, 0.05f * xp[(size_t)t * D_]);
        ip[(size_t)t * D_] = acc;
    }
}

// pack two fp32 into hi/lo bf16 pairs and store as 4B each
__device__ __forceinline__ void split_store2(__nv_bfloat16* hi, __nv_bfloat16* lo,
                                             size_t idx, float v0, float v1) {
    __nv_bfloat16 h0 = __float2bfloat16(v0);
    __nv_bfloat16 h1 = __float2bfloat16(v1);
    __nv_bfloat16 l0 = __float2bfloat16(v0 - __bfloat162float(h0));
    __nv_bfloat16 l1 = __float2bfloat16(v1 - __bfloat162float(h1));
    __nv_bfloat162 hp; hp.x = h0; hp.y = h1;
    __nv_bfloat162 lp; lp.x = l0; lp.y = l1;
    *(__nv_bfloat162*)(hi + idx) = hp;
    *(__nv_bfloat162*)(lo + idx) = lp;
}

__global__ void build_abc_kernel(const float* __restrict__ x,
                                 const float* __restrict__ kick_v)
{
    int r = blockIdx.x;
    int p = blockIdx.y;
    int t = r % T_;
    const float* par = g_params + (size_t)r * 12 + p * 4;
    float g0 = par[0], g1 = par[1], g2 = par[2], km = par[3];
    size_t base = ((size_t)p * NTOK + r) * K3;
    const float* xt = x + (size_t)r * D_;
    const float* integ = g_integral + (size_t)r * D_;
    for (int d2 = threadIdx.x; d2 < D_ / 2; d2 += blockDim.x) {
        int d = d2 * 2;
        float2 xv = *(const float2*)(xt + d);
        float2 iv = *(const float2*)(integ + d);
        float der0, der1;
        if (t > 0) {
            float2 pv = *(const float2*)(xt + d - D_);
            der0 = xv.x - pv.x; der1 = xv.y - pv.y;
        } else { der0 = 0.f; der1 = 0.f; }
        float2 kv = *(const float2*)(kick_v + p * D_ + d);
        der0 = fmaf(km, kv.x, der0);
        der1 = fmaf(km, kv.y, der1);
        split_store2(g_abc_hi, g_abc_lo, base + d,          g0 * xv.x, g0 * xv.y);
        split_store2(g_abc_hi, g_abc_lo, base + D_ + d,     g1 * iv.x, g1 * iv.y);
        split_store2(g_abc_hi, g_abc_lo, base + 2 * D_ + d, g2 * der0, g2 * der1);
    }
}

__global__ void conv_w_kernel(const float* __restrict__ Wp,
                              const float* __restrict__ Wi,
                              const float* __restrict__ Wd)
{
    size_t i2 = (size_t)blockIdx.x * blockDim.x + threadIdx.x;
    if (i2 >= (size_t)3 * 1024 * K3 / 2) return;
    size_t i = i2 * 2;
    int k = (int)(i % K3);
    size_t pn = i / K3;
    int sel = k >> 10;
    const float* src = (sel == 0) ? Wp : (sel == 1) ? Wi : Wd;
    float2 v = *(const float2*)(src + pn * 1024 + (k & 1023));
    split_store2(g_w_hi, g_w_lo, i, v.x, v.y);
}

__global__ void conv_ow_kernel(const float* __restrict__ ow)
{
    size_t i2 = (size_t)blockIdx.x * blockDim.x + threadIdx.x;
    if (i2 >= (size_t)1024 * 1024 / 2) return;
    size_t i = i2 * 2;
    float2 v = *(const float2*)(ow + i);
    split_store2(g_ow_hi, g_ow_lo, i, v.x, v.y);
}

// ============================ bf16x3 mma.sync GEMM v3 ============================
// C[M x 1024] = Ah*Bh^T + Al*Bh^T + Ah*Bl^T   (A [m][k], B=W [n][k], both k-contiguous)
// CTA tile 128(M) x 256(N), 8 warps 2x4 (warp tile 64x64), KT=64, 3-stage cp.async.
#define KT      64
#define GSTG    3
#define ROWB    144                    // 128B data + 16B skew: conflict-free ldmatrix
#define ATILE_SZ (128 * ROWB)          // 18432
#define BTILE_SZ (256 * ROWB)          // 36864
#define STAGE_SZ (ATILE_SZ + BTILE_SZ) // 55296
#define GEMM_SMEM (GSTG * STAGE_SZ)    // 165888

__device__ __forceinline__ void gemm_issue(
    const __nv_bfloat16* As, const __nv_bfloat16* Bs, int K,
    uint32_t sb, int tid, int stage, int kk, int m0, int brow0)
{
    uint32_t st = sb + stage * STAGE_SZ;
#pragma unroll
    for (int j = 0; j < 12; j++) {
        int i = tid + j * 256;             // 0..3071
        bool isB = (i >= 1024);
        int idx = isB ? i - 1024 : i;
        int row = idx >> 3, c = idx & 7;   // 8 x 16B = 128B per row
        const __nv_bfloat16* src = (isB ? Bs + (size_t)(brow0 + row) * K
                                        : As + (size_t)(m0 + row) * K) + kk + c * 8;
        uint32_t dst = st + (isB ? ATILE_SZ : 0) + row * ROWB + c * 16;
        cp_async16(dst, src);
    }
    cp_commit();
}

__global__ void __launch_bounds__(256, 1)
gemm_bf16x3(const __nv_bfloat16* __restrict__ Ah, const __nv_bfloat16* __restrict__ Al,
            const __nv_bfloat16* __restrict__ Bh, const __nv_bfloat16* __restrict__ Bl,
            float* c0, float* c1, float* c2, int kpt, int K)
{
    extern __shared__ __align__(256) char smem[];
    uint32_t sb = s2u(smem);
    int tid = threadIdx.x, lane = tid & 31, wid = tid >> 5;
    int wm = wid >> 2, wn = wid & 3;       // 2 x 4 warp grid, warp tile 64x64
    int by = blockIdx.y, bx = blockIdx.x;
    int proj = by >> 5;
    int m0 = by * 128;
    int brow0 = proj * 1024 + bx * 256;
    int NC = 3 * kpt;

    float d[4][8][4];
#pragma unroll
    for (int i = 0; i < 4; i++)
#pragma unroll
        for (int j = 0; j < 8; j++)
#pragma unroll
            for (int q = 0; q < 4; q++) d[i][j][q] = 0.f;

    uint32_t a_off = (uint32_t)((wm * 64 + (lane & 15)) * ROWB + (lane >> 4) * 16);
    uint32_t b_off = (uint32_t)(ATILE_SZ
                     + (wn * 64 + ((lane >> 4) << 3) + (lane & 7)) * ROWB
                     + ((lane >> 3) & 1) * 16);

    // producer counters (no division in the loop)
    int pterm = 0, pkc = 0;
    const __nv_bfloat16* pA = Ah;
    const __nv_bfloat16* pB = Bh;

    // prologue: 2 chunks (stages 0,1)
#pragma unroll
    for (int pr = 0; pr < 2; pr++) {
        gemm_issue(pA, pB, K, sb, tid, pr, pkc * KT, m0, brow0);
        if (++pkc == kpt) {
            pkc = 0; pterm++;
            pA = (pterm == 1) ? Al : Ah;
            pB = (pterm == 2) ? Bl : Bh;
        }
    }
    int pstage = 2;

    for (int kc = 0; kc < NC; kc++) {
        cp_wait1();
        __syncthreads();
        uint32_t st = sb + (kc % GSTG) * STAGE_SZ;
#pragma unroll
        for (int ks = 0; ks < 4; ks++) {
            uint32_t a0 = st + a_off + ks * 32;
            uint32_t ab = st + b_off + ks * 32;
            uint32_t a[4][4];
#pragma unroll
            for (int mb = 0; mb < 4; mb++)
                ldsm_x4(a[mb], a0 + mb * 16 * ROWB);
            uint32_t b[4][4];
#pragma unroll
            for (int nb = 0; nb < 4; nb++)
                ldsm_x4(b[nb], ab + nb * 16 * ROWB);
#pragma unroll
            for (int mb = 0; mb < 4; mb++)
#pragma unroll
                for (int nb = 0; nb < 4; nb++) {
                    mma_bf16(d[mb][2 * nb],     a[mb], b[nb]);
                    mma_bf16(d[mb][2 * nb + 1], a[mb], b[nb] + 2);
                }
        }
        // issue chunk kc+2 into stage (kc+2)%3 (= stage of chunk kc-1,
        // whose readers were fenced by this iteration's entry sync)
        if (pterm < 3) {
            gemm_issue(pA, pB, K, sb, tid, pstage, pkc * KT, m0, brow0);
            if (++pkc == kpt) {
                pkc = 0; pterm++;
                pA = (pterm == 1) ? Al : Ah;
                pB = (pterm == 2) ? Bl : Bh;
            }
            if (++pstage == GSTG) pstage = 0;
        } else {
            cp_commit();   // keep group accounting uniform
        }
    }

    // epilogue
    float* C = (proj == 0) ? c0 : (proj == 1) ? c1 : c2;
    int g = lane >> 2, q = lane & 3;
    int rb = (by & 31) * 128 + wm * 64;
    int cb = bx * 256 + wn * 64;
#pragma unroll
    for (int mb = 0; mb < 4; mb++) {
#pragma unroll
        for (int nt = 0; nt < 8; nt++) {
            float* cp = C + (size_t)(rb + mb * 16 + g) * 1024 + cb + nt * 8 + q * 2;
            *(float2*)cp = make_float2(d[mb][nt][0], d[mb][nt][1]);
            *(float2*)(cp + 8 * 1024) = make_float2(d[mb][nt][2], d[mb][nt][3]);
        }
    }
}

// ============================ sparse attention ============================
template<int AA>
__global__ void attn_kernel(const int* __restrict__ positions)
{
    int wid = (blockIdx.x * blockDim.x + threadIdx.x) >> 5;
    int lane = threadIdx.x & 31;
    if (wid >= B_ * H_ * T_) return;
    int t = wid % T_;
    int h = (wid / T_) % H_;
    int b = wid / (T_ * H_);

    const float* qp = g_q + ((size_t)b * T_ + t) * D_ + h * DH_;
    int d0 = lane * 2;
    float q0 = qp[d0], q1 = qp[d0 + 1];

    int nv = 1 + min(3, t);
    if (t >= 4) nv += (31 - __clz((unsigned)t)) - 1;

    float sc[AA];
    int ps[AA];
    float mx = -1e30f;
#pragma unroll
    for (int a = 0; a < AA; a++) {
        int pos = positions[t * AA + a];
        ps[a] = pos;
        const float* kp = g_k + ((size_t)b * T_ + pos) * D_ + h * DH_;
        float s = fmaf(q0, kp[d0], q1 * kp[d0 + 1]);
#pragma unroll
        for (int o = 16; o; o >>= 1) s += __shfl_xor_sync(0xffffffffu, s, o);
        s = (a < nv) ? s * 0.125f : -1e30f;
        sc[a] = s;
        mx = fmaxf(mx, s);
    }
    float sum = 0.f;
#pragma unroll
    for (int a = 0; a < AA; a++) { sc[a] = expf(sc[a] - mx); sum += sc[a]; }
    float inv = 1.f / sum;
    float o0 = 0.f, o1 = 0.f;
#pragma unroll
    for (int a = 0; a < AA; a++) {
        const float* vp = g_v + ((size_t)b * T_ + ps[a]) * D_ + h * DH_;
        float wgt = sc[a] * inv;
        o0 = fmaf(wgt, vp[d0], o0);
        o1 = fmaf(wgt, vp[d0 + 1], o1);
    }
    size_t oi = ((size_t)b * T_ + t) * D_ + h * DH_ + d0;
    split_store2(g_att_hi, g_att_lo, oi, o0, o1);
}

__global__ void attn_kernel_dyn(const int* __restrict__ positions, int A)
{
    int wid = (blockIdx.x * blockDim.x + threadIdx.x) >> 5;
    int lane = threadIdx.x & 31;
    if (wid >= B_ * H_ * T_) return;
    int t = wid % T_;
    int h = (wid / T_) % H_;
    int b = wid / (T_ * H_);
    const float* qp = g_q + ((size_t)b * T_ + t) * D_ + h * DH_;
    int d0 = lane * 2;
    float q0 = qp[d0], q1 = qp[d0 + 1];
    int nv = 1 + min(3, t);
    if (t >= 4) nv += (31 - __clz((unsigned)t)) - 1;
    float sc[32]; int ps[32];
    float mx = -1e30f;
    for (int a = 0; a < A; a++) {
        int pos = positions[t * A + a];
        ps[a] = pos;
        const float* kp = g_k + ((size_t)b * T_ + pos) * D_ + h * DH_;
        float s = fmaf(q0, kp[d0], q1 * kp[d0 + 1]);
        for (int o = 16; o; o >>= 1) s += __shfl_xor_sync(0xffffffffu, s, o);
        s = (a < nv) ? s * 0.125f : -1e30f;
        sc[a] = s; mx = fmaxf(mx, s);
    }
    float sum = 0.f;
    for (int a = 0; a < A; a++) { sc[a] = expf(sc[a] - mx); sum += sc[a]; }
    float inv = 1.f / sum;
    float o0 = 0.f, o1 = 0.f;
    for (int a = 0; a < A; a++) {
        const float* vp = g_v + ((size_t)b * T_ + ps[a]) * D_ + h * DH_;
        float wgt = sc[a] * inv;
        o0 = fmaf(wgt, vp[d0], o0);
        o1 = fmaf(wgt, vp[d0 + 1], o1);
    }
    size_t oi = ((size_t)b * T_ + t) * D_ + h * DH_ + d0;
    split_store2(g_att_hi, g_att_lo, oi, o0, o1);
}

// ============================ launcher ============================
extern "C" void kernel_launch(void* const* d_in, const int* in_sizes, int n_in,
                              void* d_out, int out_size)
{
    const float* x       = (const float*)d_in[0];
    const float* qkv_Wp  = (const float*)d_in[1];
    const float* qkv_Wi  = (const float*)d_in[2];
    const float* qkv_Wd  = (const float*)d_in[3];
    const float* gate_w  = (const float*)d_in[4];
    const float* gate_b  = (const float*)d_in[5];
    const float* kick_v  = (const float*)d_in[6];
    const float* kick_w  = (const float*)d_in[7];
    const float* kick_b  = (const float*)d_in[8];
    const float* o_w     = (const float*)d_in[9];
    const int*   positions = (const int*)d_in[10];
    int A = in_sizes[10] / T_;

    float* out = (float*)d_out;

    void *p_abc_hi, *p_abc_lo, *p_w_hi, *p_w_lo, *p_ow_hi, *p_ow_lo;
    void *p_q, *p_k, *p_v, *p_att_hi, *p_att_lo;
    cudaGetSymbolAddress(&p_abc_hi, g_abc_hi);
    cudaGetSymbolAddress(&p_abc_lo, g_abc_lo);
    cudaGetSymbolAddress(&p_w_hi, g_w_hi);
    cudaGetSymbolAddress(&p_w_lo, g_w_lo);
    cudaGetSymbolAddress(&p_ow_hi, g_ow_hi);
    cudaGetSymbolAddress(&p_ow_lo, g_ow_lo);
    cudaGetSymbolAddress(&p_q, g_q);
    cudaGetSymbolAddress(&p_k, g_k);
    cudaGetSymbolAddress(&p_v, g_v);
    cudaGetSymbolAddress(&p_att_hi, g_att_hi);
    cudaGetSymbolAddress(&p_att_lo, g_att_lo);

    cudaFuncSetAttribute(gemm_bf16x3, cudaFuncAttributeMaxDynamicSharedMemorySize, GEMM_SMEM);

    // 1. per-token gates / kick / stagnation
    token_stats_kernel<<<NTOK, 128>>>(x, gate_w, gate_b, kick_w, kick_b);
    // 2. EMA integral
    ema_kernel<<<(B_ * D_ + 255) / 256, 256>>>(x);
    // 3. weight hi/lo conversion (vectorized x2)
    conv_w_kernel<<<(3 * 1024 * K3 / 2 + 255) / 256, 256>>>(qkv_Wp, qkv_Wi, qkv_Wd);
    conv_ow_kernel<<<(1024 * 1024 / 2 + 255) / 256, 256>>>(o_w);
    // 4. gated GEMM inputs (hi/lo bf16)
    dim3 gb(NTOK, 3);
    build_abc_kernel<<<gb, 256>>>(x, kick_v);
    // 5. projection GEMMs: grid (1024/256, 3*4096/128) = (4, 96)
    dim3 pgrid(1024 / 256, 3 * (NTOK / 128));
    gemm_bf16x3<<<pgrid, 256, GEMM_SMEM>>>(
        (const __nv_bfloat16*)p_abc_hi, (const __nv_bfloat16*)p_abc_lo,
        (const __nv_bfloat16*)p_w_hi, (const __nv_bfloat16*)p_w_lo,
        (float*)p_q, (float*)p_k, (float*)p_v, K3 / KT, K3);
    // 6. sparse dilated attention
    int nwarps = B_ * H_ * T_;
    int nblocks = nwarps / 4;
    if (A == 15)
        attn_kernel<15><<<nblocks, 128>>>(positions);
    else
        attn_kernel_dyn<<<nblocks, 128>>>(positions, A);
    // 7. output projection: grid (4, 32)
    dim3 ogrid(1024 / 256, NTOK / 128);
    gemm_bf16x3<<<ogrid, 256, GEMM_SMEM>>>(
        (const __nv_bfloat16*)p_att_hi, (const __nv_bfloat16*)p_att_lo,
        (const __nv_bfloat16*)p_ow_hi, (const __nv_bfloat16*)p_ow_lo,
        out, out, out, D_ / KT, D_);
}